// round 10
// baseline (speedup 1.0000x reference)
#include <cuda_runtime.h>
#include <cuda_fp16.h>
#include <cstdint>

#define HN 16
#define DD 64
#define BQ 64
#define BK 64
#define NT 256
#define MAXT 3072
#define QSCALE 0.1803368801111f   // (1/8) * log2(e)

// per-stage smem layout (bytes)
#define S_K   0          // K fp16 [64][64], swizzled 128B rows = 8192
#define S_V   8192       // V fp16 same = 8192
#define S_SEG 16384      // 64 ints = 256
#define STG_BYTES 16640
#define GSTRIDE (2 * STG_BYTES)       // per-group region (2 stages)
#define SMEM_BYTES (2 * GSTRIDE)      // 66560

__device__ __half KH[MAXT * HN * DD];
__device__ __half VH[MAXT * HN * DD];
__device__ int SEG[MAXT];

__device__ __forceinline__ float ex2f(float x) {
    float y; asm("ex2.approx.ftz.f32 %0, %1;" : "=f"(y) : "f"(x)); return y;
}
__device__ __forceinline__ uint32_t packh2(float lo, float hi) {
    half2 h = __floats2half2_rn(lo, hi);
    return *(uint32_t*)&h;
}
__device__ __forceinline__ void mma16(float* c, const uint32_t* a, uint32_t b0, uint32_t b1) {
    asm volatile("mma.sync.aligned.m16n8k16.row.col.f32.f16.f16.f32 "
                 "{%0,%1,%2,%3}, {%4,%5,%6,%7}, {%8,%9}, {%0,%1,%2,%3};"
                 : "+f"(c[0]), "+f"(c[1]), "+f"(c[2]), "+f"(c[3])
                 : "r"(a[0]), "r"(a[1]), "r"(a[2]), "r"(a[3]), "r"(b0), "r"(b1));
}
__device__ __forceinline__ void ldsm4(uint32_t* r, uint32_t addr) {
    asm volatile("ldmatrix.sync.aligned.m8n8.x4.shared.b16 {%0,%1,%2,%3}, [%4];"
                 : "=r"(r[0]), "=r"(r[1]), "=r"(r[2]), "=r"(r[3]) : "r"(addr));
}
__device__ __forceinline__ void ldsm4t(uint32_t* r, uint32_t addr) {
    asm volatile("ldmatrix.sync.aligned.m8n8.x4.trans.shared.b16 {%0,%1,%2,%3}, [%4];"
                 : "=r"(r[0]), "=r"(r[1]), "=r"(r[2]), "=r"(r[3]) : "r"(addr));
}
__device__ __forceinline__ uint32_t s2u(const void* p) {
    uint32_t a;
    asm("{ .reg .u64 t; cvta.to.shared.u64 t, %1; cvt.u32.u64 %0, t; }" : "=r"(a) : "l"(p));
    return a;
}
__device__ __forceinline__ void cpasync16(uint32_t saddr, const void* gaddr) {
    asm volatile("cp.async.cg.shared.global [%0], [%1], 16;" :: "r"(saddr), "l"(gaddr));
}
#define CP_COMMIT() asm volatile("cp.async.commit_group;" ::: "memory")
#define CP_WAIT0()  asm volatile("cp.async.wait_group 0;" ::: "memory")
#define GBAR(id) asm volatile("bar.sync %0, 128;" :: "r"(id) : "memory")

// ---- prep: K,V fp32 [t][h][d] -> fp16 [h][t][d]; SEG[t] ----
__global__ void prep(const float* __restrict__ k, const float* __restrict__ v,
                     const int* __restrict__ cu, int T, int ncu)
{
    int gid = blockIdx.x * 256 + threadIdx.x;     // T*HN*16 threads
    int t = gid >> 8, rem = gid & 255;
    int h = rem >> 4, d4 = rem & 15;
    size_t src = (size_t)t * (HN * DD) + h * DD + d4 * 4;
    size_t dst = ((size_t)h * T + t) * DD + d4 * 4;
    float4 kv = *(const float4*)(k + src);
    float4 vv = *(const float4*)(v + src);
    *(uint2*)(KH + dst) = make_uint2(packh2(kv.x, kv.y), packh2(kv.z, kv.w));
    *(uint2*)(VH + dst) = make_uint2(packh2(vv.x, vv.y), packh2(vv.z, vv.w));
    if (gid < T) {
        int s = 0;
        for (int i = 1; i < ncu - 1; i++) s += (cu[i] <= gid);
        SEG[gid] = s;
    }
}

__global__ __launch_bounds__(NT, 2) void varlen_attn_h5(
    const float* __restrict__ qg, const int* __restrict__ cuk,
    float* __restrict__ out, int T, int ncu)
{
    extern __shared__ char smc[];
    const uint32_t sb = s2u(smc);

    const int tid  = threadIdx.x;
    const int w    = tid >> 5;
    const int lane = tid & 31;
    const int g    = lane >> 2;
    const int tig  = lane & 3;
    const int grp  = w >> 2;        // warp-group 0 / 1
    const int wg   = w & 3;         // warp within group
    const int gtid = tid & 127;
    const int h  = blockIdx.y;
    const int q0 = blockIdx.x * BQ;

    // ldmatrix lane constants
    const int r0    = (lane & 7) + 8 * ((lane >> 3) & 1);
    const int cbase = lane >> 4;
    const int xorv  = lane & 7;

    const uint32_t gbase = sb + grp * GSTRIDE;

    const int t0g = q0 + wg * 16 + g;
    const int t1g = t0g + 8;
    const int qs0 = SEG[t0g];
    const int qs1 = SEG[t1g];
    const int kbeg = cuk[SEG[q0]];
    const int kend = cuk[SEG[min(q0 + BQ - 1, T - 1)] + 1];
    const int kt0 = (kbeg >> 6) << 6;
    const int ntl = ((kend - 1) >> 6) - (kbeg >> 6) + 1;
    const int nj = (ntl - grp + 1) >> 1;       // tiles for this group (even/odd walk)

    const __half* kh = KH + (size_t)h * T * DD;
    const __half* vh = VH + (size_t)h * T * DD;

    // ---- prologue: issue this group's tile 0 ----
    if (nj > 0) {
        const int kt = kt0 + grp * BK;
        #pragma unroll
        for (int i = 0; i < 4; i++) {
            int idx = gtid + i * 128;          // 0..511
            int r = idx >> 3, c = idx & 7;
            uint32_t so = (uint32_t)(r * 128 + ((c ^ (r & 7)) << 4));
            cpasync16(gbase + S_K + so, kh + (size_t)(kt + r) * DD + c * 8);
            cpasync16(gbase + S_V + so, vh + (size_t)(kt + r) * DD + c * 8);
        }
        if (gtid < 16) cpasync16(gbase + S_SEG + gtid * 16, SEG + kt + gtid * 4);
    }
    CP_COMMIT();

    // ---- Q fragments from fp32 gmem ----
    uint32_t qaf[4][4];
    {
        const float* qp0 = qg + (size_t)t0g * (HN * DD) + h * DD;
        const float* qp1 = qg + (size_t)t1g * (HN * DD) + h * DD;
        #pragma unroll
        for (int kk = 0; kk < 4; kk++) {
            int d0 = kk * 16 + 2 * tig;
            float2 a = *(const float2*)(qp0 + d0);
            float2 b = *(const float2*)(qp1 + d0);
            float2 c = *(const float2*)(qp0 + d0 + 8);
            float2 d = *(const float2*)(qp1 + d0 + 8);
            qaf[kk][0] = packh2(a.x * QSCALE, a.y * QSCALE);
            qaf[kk][1] = packh2(b.x * QSCALE, b.y * QSCALE);
            qaf[kk][2] = packh2(c.x * QSCALE, c.y * QSCALE);
            qaf[kk][3] = packh2(d.x * QSCALE, d.y * QSCALE);
        }
    }

    float oacc[8][4];
    #pragma unroll
    for (int n = 0; n < 8; n++)
        #pragma unroll
        for (int j = 0; j < 4; j++) oacc[n][j] = 0.f;
    float l0 = 0.f, l1 = 0.f;

    for (int j = 0; j < nj; j++) {
        const uint32_t stg = gbase + (j & 1) * STG_BYTES;

        CP_WAIT0();
        GBAR(1 + grp);      // group-local barrier: tile ready, prev readers done

        if (j + 1 < nj) {
            const int ktn = kt0 + (2 * (j + 1) + grp) * BK;
            const uint32_t st2 = gbase + ((j + 1) & 1) * STG_BYTES;
            #pragma unroll
            for (int i = 0; i < 4; i++) {
                int idx = gtid + i * 128;
                int r = idx >> 3, c = idx & 7;
                uint32_t so = (uint32_t)(r * 128 + ((c ^ (r & 7)) << 4));
                cpasync16(st2 + S_K + so, kh + (size_t)(ktn + r) * DD + c * 8);
                cpasync16(st2 + S_V + so, vh + (size_t)(ktn + r) * DD + c * 8);
            }
            if (gtid < 16) cpasync16(st2 + S_SEG + gtid * 16, SEG + ktn + gtid * 4);
        }
        CP_COMMIT();

        // ---- S = Q K^T ----
        float sacc[8][4];
        #pragma unroll
        for (int n = 0; n < 8; n++)
            #pragma unroll
            for (int jj = 0; jj < 4; jj++) sacc[n][jj] = 0.f;

        #pragma unroll
        for (int kk = 0; kk < 4; kk++) {
            #pragma unroll
            for (int np = 0; np < 4; np++) {
                uint32_t kf[4];
                uint32_t addr = stg + S_K + (uint32_t)((r0 + np * 16) * 128 +
                                (((2 * kk + cbase) ^ xorv) << 4));
                ldsm4(kf, addr);
                mma16(sacc[2 * np],     qaf[kk], kf[0], kf[2]);
                mma16(sacc[2 * np + 1], qaf[kk], kf[1], kf[3]);
            }
        }

        // ---- mask + exp2 + pack ----
        uint32_t af[4][4];
        #pragma unroll
        for (int kk = 0; kk < 4; kk++) {
            #pragma unroll
            for (int hf = 0; hf < 2; hf++) {
                int jj = 2 * kk + hf;
                int kc = jj * 8 + 2 * tig;
                const int2 ks2 = *(const int2*)(smc + (stg - sb) + S_SEG + kc * 4);
                float p00 = (ks2.x == qs0) ? ex2f(sacc[jj][0]) : 0.f;
                float p01 = (ks2.y == qs0) ? ex2f(sacc[jj][1]) : 0.f;
                float p10 = (ks2.x == qs1) ? ex2f(sacc[jj][2]) : 0.f;
                float p11 = (ks2.y == qs1) ? ex2f(sacc[jj][3]) : 0.f;
                l0 += p00 + p01;
                l1 += p10 + p11;
                af[kk][2 * hf + 0] = packh2(p00, p01);
                af[kk][2 * hf + 1] = packh2(p10, p11);
            }
        }

        // ---- O += P V ----
        #pragma unroll
        for (int kk = 0; kk < 4; kk++) {
            #pragma unroll
            for (int np = 0; np < 4; np++) {
                uint32_t vf[4];
                uint32_t addr = stg + S_V + (uint32_t)((r0 + kk * 16) * 128 +
                                (((2 * np + cbase) ^ xorv) << 4));
                ldsm4t(vf, addr);
                mma16(oacc[2 * np],     af[kk], vf[0], vf[1]);
                mma16(oacc[2 * np + 1], af[kk], vf[2], vf[3]);
            }
        }
    }

    // ---- row sums within 4-lane group ----
    l0 += __shfl_xor_sync(0xffffffffu, l0, 1);
    l0 += __shfl_xor_sync(0xffffffffu, l0, 2);
    l1 += __shfl_xor_sync(0xffffffffu, l1, 1);
    l1 += __shfl_xor_sync(0xffffffffu, l1, 2);

    // ---- combine the two groups' partials (additive: no online max) ----
    float* Ocmb = (float*)(smc + GSTRIDE);                 // [64][66] floats (padded)
    float* Lcmb = (float*)(smc + GSTRIDE + 64 * 66 * 4);   // [64]
    const int row0 = wg * 16 + g;

    __syncthreads();     // all compute + pipeline reads complete
    if (grp == 1) {
        #pragma unroll
        for (int n = 0; n < 8; n++) {
            int c = n * 8 + 2 * tig;
            *(float2*)&Ocmb[row0 * 66 + c]       = make_float2(oacc[n][0], oacc[n][1]);
            *(float2*)&Ocmb[(row0 + 8) * 66 + c] = make_float2(oacc[n][2], oacc[n][3]);
        }
        if (tig == 0) { Lcmb[row0] = l0; Lcmb[row0 + 8] = l1; }
    }
    __syncthreads();
    if (grp == 0) {
        float i0 = 1.f / (l0 + Lcmb[row0]);
        float i1 = 1.f / (l1 + Lcmb[row0 + 8]);
        float* o0 = out + (size_t)t0g * (HN * DD) + h * DD;
        float* o1 = out + (size_t)t1g * (HN * DD) + h * DD;
        #pragma unroll
        for (int n = 0; n < 8; n++) {
            int c = n * 8 + 2 * tig;
            float2 a = *(const float2*)&Ocmb[row0 * 66 + c];
            float2 b = *(const float2*)&Ocmb[(row0 + 8) * 66 + c];
            *(float2*)(o0 + c) = make_float2((oacc[n][0] + a.x) * i0, (oacc[n][1] + a.y) * i0);
            *(float2*)(o1 + c) = make_float2((oacc[n][2] + b.x) * i1, (oacc[n][3] + b.y) * i1);
        }
    }
}

extern "C" void kernel_launch(void* const* d_in, const int* in_sizes, int n_in,
                              void* d_out, int out_size)
{
    const float* q = (const float*)d_in[0];
    const float* k = (const float*)d_in[1];
    const float* v = (const float*)d_in[2];
    const int* cuk = (const int*)d_in[4];

    int T = in_sizes[0] / (HN * DD);
    int ncu = in_sizes[3];

    cudaFuncSetAttribute(varlen_attn_h5,
                         cudaFuncAttributeMaxDynamicSharedMemorySize, SMEM_BYTES);

    prep<<<(T * HN * 16) / 256, 256>>>(k, v, cuk, T, ncu);

    dim3 grid((T + BQ - 1) / BQ, HN);
    varlen_attn_h5<<<grid, NT, SMEM_BYTES>>>(q, cuk, (float*)d_out, T, ncu);
}

// round 11
// speedup vs baseline: 1.1141x; 1.1141x over previous
#include <cuda_runtime.h>
#include <cuda_fp16.h>
#include <cstdint>

#define HN 16
#define DD 64
#define BQ 64
#define BK 64
#define NT 128
#define MAXT 3072
#define QSCALE 0.1803368801111f   // (1/8) * log2(e)
#define NEGH2 0xFBFFFBFFu          // half2 {-65504, -65504}
#define ONESH2 0x3C003C00u         // half2 {1, 1}

// per-stage smem layout (bytes)
#define S_K   0          // K fp16 [64][64], swizzled 128B rows = 8192
#define S_V   8192       // V fp16 same = 8192
#define S_SEG 16384      // 64 ints = 256
#define STG_BYTES 16640
#define SMEM_BYTES (2 * STG_BYTES)

__device__ __half KH[MAXT * HN * DD];
__device__ __half VH[MAXT * HN * DD];
__device__ int SEG[MAXT];

__device__ __forceinline__ uint32_t ex2h2(uint32_t x) {
    uint32_t y; asm("ex2.approx.f16x2 %0, %1;" : "=r"(y) : "r"(x)); return y;
}
__device__ __forceinline__ uint32_t packh2(float lo, float hi) {
    half2 h = __floats2half2_rn(lo, hi);
    return *(uint32_t*)&h;
}
// fp32-accum fp16 mma
__device__ __forceinline__ void mma16(float* c, const uint32_t* a, uint32_t b0, uint32_t b1) {
    asm volatile("mma.sync.aligned.m16n8k16.row.col.f32.f16.f16.f32 "
                 "{%0,%1,%2,%3}, {%4,%5,%6,%7}, {%8,%9}, {%0,%1,%2,%3};"
                 : "+f"(c[0]), "+f"(c[1]), "+f"(c[2]), "+f"(c[3])
                 : "r"(a[0]), "r"(a[1]), "r"(a[2]), "r"(a[3]), "r"(b0), "r"(b1));
}
// fp16-accum fp16 mma (D/C = 2 regs of half2)
__device__ __forceinline__ void mma16h(uint32_t* d, const uint32_t* a, uint32_t b0, uint32_t b1) {
    asm volatile("mma.sync.aligned.m16n8k16.row.col.f16.f16.f16.f16 "
                 "{%0,%1}, {%2,%3,%4,%5}, {%6,%7}, {%0,%1};"
                 : "+r"(d[0]), "+r"(d[1])
                 : "r"(a[0]), "r"(a[1]), "r"(a[2]), "r"(a[3]), "r"(b0), "r"(b1));
}
__device__ __forceinline__ void ldsm4(uint32_t* r, uint32_t addr) {
    asm volatile("ldmatrix.sync.aligned.m8n8.x4.shared.b16 {%0,%1,%2,%3}, [%4];"
                 : "=r"(r[0]), "=r"(r[1]), "=r"(r[2]), "=r"(r[3]) : "r"(addr));
}
__device__ __forceinline__ void ldsm4t(uint32_t* r, uint32_t addr) {
    asm volatile("ldmatrix.sync.aligned.m8n8.x4.trans.shared.b16 {%0,%1,%2,%3}, [%4];"
                 : "=r"(r[0]), "=r"(r[1]), "=r"(r[2]), "=r"(r[3]) : "r"(addr));
}
__device__ __forceinline__ uint32_t s2u(const void* p) {
    uint32_t a;
    asm("{ .reg .u64 t; cvta.to.shared.u64 t, %1; cvt.u32.u64 %0, t; }" : "=r"(a) : "l"(p));
    return a;
}
__device__ __forceinline__ void cpasync16(uint32_t saddr, const void* gaddr) {
    asm volatile("cp.async.cg.shared.global [%0], [%1], 16;" :: "r"(saddr), "l"(gaddr));
}
#define CP_COMMIT() asm volatile("cp.async.commit_group;" ::: "memory")
#define CP_WAIT0()  asm volatile("cp.async.wait_group 0;" ::: "memory")

// ---- prep: K,V fp32 [t][h][d] -> fp16 [h][t][d]; SEG[t] ----
__global__ void prep(const float* __restrict__ k, const float* __restrict__ v,
                     const int* __restrict__ cu, int T, int ncu)
{
    int gid = blockIdx.x * 256 + threadIdx.x;
    int t = gid >> 8, rem = gid & 255;
    int h = rem >> 4, d4 = rem & 15;
    size_t src = (size_t)t * (HN * DD) + h * DD + d4 * 4;
    size_t dst = ((size_t)h * T + t) * DD + d4 * 4;
    float4 kv = *(const float4*)(k + src);
    float4 vv = *(const float4*)(v + src);
    *(uint2*)(KH + dst) = make_uint2(packh2(kv.x, kv.y), packh2(kv.z, kv.w));
    *(uint2*)(VH + dst) = make_uint2(packh2(vv.x, vv.y), packh2(vv.z, vv.w));
    if (gid < T) {
        int s = 0;
        for (int i = 1; i < ncu - 1; i++) s += (cu[i] <= gid);
        SEG[gid] = s;
    }
}

__global__ __launch_bounds__(NT, 4) void varlen_attn_h6(
    const float* __restrict__ qg, const int* __restrict__ cuk,
    float* __restrict__ out, int T, int ncu)
{
    extern __shared__ char smc[];
    const uint32_t sb = s2u(smc);

    const int tid  = threadIdx.x;
    const int w    = tid >> 5;
    const int lane = tid & 31;
    const int g    = lane >> 2;
    const int tig  = lane & 3;
    const int h  = blockIdx.y;
    const int q0 = blockIdx.x * BQ;

    const int r0    = (lane & 7) + 8 * ((lane >> 3) & 1);
    const int cbase = lane >> 4;
    const int xorv  = lane & 7;

    const int t0g = q0 + w * 16 + g;
    const int t1g = t0g + 8;
    const int qs0 = SEG[t0g];
    const int qs1 = SEG[t1g];
    const int kbeg = cuk[SEG[q0]];
    const int kend = cuk[SEG[min(q0 + BQ - 1, T - 1)] + 1];
    const int kt0 = (kbeg >> 6) << 6;
    const int ntl = ((kend - 1) >> 6) - (kbeg >> 6) + 1;

    const __half* kh = KH + (size_t)h * T * DD;
    const __half* vh = VH + (size_t)h * T * DD;

    // ---- issue tile 0 into stage 0 ----
    {
        #pragma unroll
        for (int i = 0; i < 4; i++) {
            int idx = tid + i * NT;
            int r = idx >> 3, c = idx & 7;
            uint32_t so = (uint32_t)(r * 128 + ((c ^ (r & 7)) << 4));
            cpasync16(sb + S_K + so, kh + (size_t)(kt0 + r) * DD + c * 8);
            cpasync16(sb + S_V + so, vh + (size_t)(kt0 + r) * DD + c * 8);
        }
        if (tid < 16) cpasync16(sb + S_SEG + tid * 16, SEG + kt0 + tid * 4);
        CP_COMMIT();
    }

    // ---- Q fragments from fp32 gmem (pre-scaled) ----
    uint32_t qaf[4][4];
    {
        const float* qp0 = qg + (size_t)t0g * (HN * DD) + h * DD;
        const float* qp1 = qg + (size_t)t1g * (HN * DD) + h * DD;
        #pragma unroll
        for (int kk = 0; kk < 4; kk++) {
            int d0 = kk * 16 + 2 * tig;
            float2 a = *(const float2*)(qp0 + d0);
            float2 b = *(const float2*)(qp1 + d0);
            float2 c = *(const float2*)(qp0 + d0 + 8);
            float2 d = *(const float2*)(qp1 + d0 + 8);
            qaf[kk][0] = packh2(a.x * QSCALE, a.y * QSCALE);
            qaf[kk][1] = packh2(b.x * QSCALE, b.y * QSCALE);
            qaf[kk][2] = packh2(c.x * QSCALE, c.y * QSCALE);
            qaf[kk][3] = packh2(d.x * QSCALE, d.y * QSCALE);
        }
    }

    float oacc[8][4];
    #pragma unroll
    for (int n = 0; n < 8; n++)
        #pragma unroll
        for (int j = 0; j < 4; j++) oacc[n][j] = 0.f;
    float lc[4] = {0.f, 0.f, 0.f, 0.f};

    for (int it = 0; it < ntl; it++) {
        const uint32_t stg = sb + (it & 1) * STG_BYTES;

        CP_WAIT0();
        __syncthreads();

        if (it + 1 < ntl) {
            const int ktn = kt0 + (it + 1) * BK;
            const uint32_t st2 = sb + ((it + 1) & 1) * STG_BYTES;
            #pragma unroll
            for (int i = 0; i < 4; i++) {
                int idx = tid + i * NT;
                int r = idx >> 3, c = idx & 7;
                uint32_t so = (uint32_t)(r * 128 + ((c ^ (r & 7)) << 4));
                cpasync16(st2 + S_K + so, kh + (size_t)(ktn + r) * DD + c * 8);
                cpasync16(st2 + S_V + so, vh + (size_t)(ktn + r) * DD + c * 8);
            }
            if (tid < 16) cpasync16(st2 + S_SEG + tid * 16, SEG + ktn + tid * 4);
        }
        CP_COMMIT();

        // ---- S = Q K^T with f16 accumulators ----
        uint32_t sacc[8][2];
        #pragma unroll
        for (int n = 0; n < 8; n++) { sacc[n][0] = 0u; sacc[n][1] = 0u; }

        #pragma unroll
        for (int kk = 0; kk < 4; kk++) {
            #pragma unroll
            for (int np = 0; np < 4; np++) {
                uint32_t kf[4];
                uint32_t addr = stg + S_K + (uint32_t)((r0 + np * 16) * 128 +
                                (((2 * kk + cbase) ^ xorv) << 4));
                ldsm4(kf, addr);
                mma16h(sacc[2 * np],     qaf[kk], kf[0], kf[2]);
                mma16h(sacc[2 * np + 1], qaf[kk], kf[1], kf[3]);
            }
        }

        // ---- mask (bit-select) + ex2.f16x2 in place ----
        #pragma unroll
        for (int j = 0; j < 8; j++) {
            int kc = j * 8 + 2 * tig;
            const int2 ks2 = *(const int2*)(smc + (stg - sb) + S_SEG + kc * 4);
            uint32_t m0 = (ks2.x == qs0 ? 0x0000FFFFu : 0u) | (ks2.y == qs0 ? 0xFFFF0000u : 0u);
            uint32_t m1 = (ks2.x == qs1 ? 0x0000FFFFu : 0u) | (ks2.y == qs1 ? 0xFFFF0000u : 0u);
            sacc[j][0] = ex2h2((sacc[j][0] & m0) | (NEGH2 & ~m0));
            sacc[j][1] = ex2h2((sacc[j][1] & m1) | (NEGH2 & ~m1));
        }

        // ---- l += P * ones  (row sums at tensor rate; every lane gets full sum) ----
        #pragma unroll
        for (int kk = 0; kk < 4; kk++) {
            uint32_t a[4] = { sacc[2 * kk][0], sacc[2 * kk][1],
                              sacc[2 * kk + 1][0], sacc[2 * kk + 1][1] };
            mma16(lc, a, ONESH2, ONESH2);
        }

        // ---- O += P V ----
        #pragma unroll
        for (int kk = 0; kk < 4; kk++) {
            uint32_t a[4] = { sacc[2 * kk][0], sacc[2 * kk][1],
                              sacc[2 * kk + 1][0], sacc[2 * kk + 1][1] };
            #pragma unroll
            for (int np = 0; np < 4; np++) {
                uint32_t vf[4];
                uint32_t addr = stg + S_V + (uint32_t)((r0 + kk * 16) * 128 +
                                (((2 * np + cbase) ^ xorv) << 4));
                ldsm4t(vf, addr);
                mma16(oacc[2 * np],     a, vf[0], vf[1]);
                mma16(oacc[2 * np + 1], a, vf[2], vf[3]);
            }
        }
    }

    // ---- epilogue: lc[0] = row-g sum, lc[2] = row-(g+8) sum (all lanes) ----
    float i0 = 1.f / lc[0];
    float i1 = 1.f / lc[2];

    float* o0 = out + (size_t)t0g * (HN * DD) + h * DD;
    float* o1 = out + (size_t)t1g * (HN * DD) + h * DD;
    #pragma unroll
    for (int n = 0; n < 8; n++) {
        int c = n * 8 + 2 * tig;
        *(float2*)(o0 + c) = make_float2(oacc[n][0] * i0, oacc[n][1] * i0);
        *(float2*)(o1 + c) = make_float2(oacc[n][2] * i1, oacc[n][3] * i1);
    }
}

extern "C" void kernel_launch(void* const* d_in, const int* in_sizes, int n_in,
                              void* d_out, int out_size)
{
    const float* q = (const float*)d_in[0];
    const float* k = (const float*)d_in[1];
    const float* v = (const float*)d_in[2];
    const int* cuk = (const int*)d_in[4];

    int T = in_sizes[0] / (HN * DD);
    int ncu = in_sizes[3];

    cudaFuncSetAttribute(varlen_attn_h6,
                         cudaFuncAttributeMaxDynamicSharedMemorySize, SMEM_BYTES);

    prep<<<(T * HN * 16) / 256, 256>>>(k, v, cuk, T, ncu);

    dim3 grid((T + BQ - 1) / BQ, HN);
    varlen_attn_h6<<<grid, NT, SMEM_BYTES>>>(q, cuk, (float*)d_out, T, ncu);
}